// round 16
// baseline (speedup 1.0000x reference)
#include <cuda_runtime.h>
#include <cuda_fp16.h>
#include <math.h>
#include <stdint.h>

#define B_  16
#define D_  96
#define T_  512
#define H_  1024
#define BD_ (B_*B_*6)   // 1536 rows (B_*D_)

// ---- scratch ----
__device__ float  g_A[B_*D_*D_];    // softmax corr (fp32)
__device__ __half g_x1h[B_*D_*T_];  // attn+res in fp16 (GEMM1 A + GEMM2 residual)
__device__ float  g_bnstats[2*D_];  // per-channel sum / sumsq (atomic, zeroed in k_pre)
__device__ float  g_bnscale[D_];
__device__ float  g_bnoff[D_];
__device__ float  g_colsum[H_];     // per-col sum of W1
__device__ __half g_h[B_*D_*H_];    // GELU output fp16
__device__ float  g_y[2*B_*D_*T_];  // GEMM2 split-K partials (fp32)
__device__ __half g_w1h[T_*H_];     // W1 [T][H] fp16
__device__ __half g_w2h[H_*T_];     // W2 [H][T] fp16

extern __shared__ char dyn_smem[];

__device__ __forceinline__ float warp_sum(float v){
    #pragma unroll
    for(int o=16;o>0;o>>=1) v += __shfl_xor_sync(0xffffffffu, v, o);
    return v;
}
__device__ __forceinline__ float warp_max(float v){
    #pragma unroll
    for(int o=16;o>0;o>>=1) v = fmaxf(v, __shfl_xor_sync(0xffffffffu, v, o));
    return v;
}
__device__ __forceinline__ uint32_t smem_u32(const void* p){
    uint32_t a;
    asm("{ .reg .u64 t; cvta.to.shared.u64 t, %1; cvt.u32.u64 %0, t; }" : "=r"(a) : "l"(p));
    return a;
}
__device__ __forceinline__ void mma_f16(float4& d, const uint32_t a[4], uint32_t b0, uint32_t b1){
    asm volatile("mma.sync.aligned.m16n8k16.row.col.f32.f16.f16.f32 "
        "{%0,%1,%2,%3}, {%4,%5,%6,%7}, {%8,%9}, {%0,%1,%2,%3};"
        : "+f"(d.x), "+f"(d.y), "+f"(d.z), "+f"(d.w)
        : "r"(a[0]), "r"(a[1]), "r"(a[2]), "r"(a[3]), "r"(b0), "r"(b1));
}
__device__ __forceinline__ void ldsm_x4(uint32_t* r, uint32_t addr){
    asm volatile("ldmatrix.sync.aligned.m8n8.x4.shared.b16 {%0,%1,%2,%3}, [%4];"
        : "=r"(r[0]), "=r"(r[1]), "=r"(r[2]), "=r"(r[3]) : "r"(addr));
}
__device__ __forceinline__ void ldsm_x4t(uint32_t* r, uint32_t addr){
    asm volatile("ldmatrix.sync.aligned.m8n8.x4.trans.shared.b16 {%0,%1,%2,%3}, [%4];"
        : "=r"(r[0]), "=r"(r[1]), "=r"(r[2]), "=r"(r[3]) : "r"(addr));
}
__device__ __forceinline__ void cp16(uint32_t dst, const void* src){
    asm volatile("cp.async.ca.shared.global [%0], [%1], 16;" :: "r"(dst), "l"(src));
}
#define CP_COMMIT() asm volatile("cp.async.commit_group;" ::: "memory")
#define CP_WAIT1()  asm volatile("cp.async.wait_group 1;" ::: "memory")
#define CP_WAIT0()  asm volatile("cp.async.wait_group 0;" ::: "memory")

// K0: weight convert + corr softmax + colsum(W1) + zero bnstats. grid 277 x 256.
__global__ void k_pre(const float* __restrict__ W1, __half* __restrict__ W1h,
                      const float* __restrict__ W2, __half* __restrict__ W2h,
                      const float* __restrict__ res){
    int bid = blockIdx.x;
    if (bid < 256){
        const float* W = (bid < 128) ? W1 : W2;
        __half* Wh = (bid < 128) ? W1h : W2h;
        int base = (bid & 127) * 4096;
        #pragma unroll
        for (int i = 0; i < 4; i++){
            int idx = base + (threadIdx.x + i*256)*4;
            float4 v = *(const float4*)&W[idx];
            *(__half2*)&Wh[idx]     = __floats2half2_rn(v.x, v.y);
            *(__half2*)&Wh[idx + 2] = __floats2half2_rn(v.z, v.w);
        }
        return;
    }
    if (bid < 272){
        // ---- corr softmax for batch b ----
        __shared__ float s[D_];
        int b = bid - 256;
        int w = threadIdx.x >> 5, lane = threadIdx.x & 31;
        for (int r = w; r < D_; r += 8){
            const float4* p = (const float4*)(res + (b*D_ + r)*T_);
            float v = 0.f;
            #pragma unroll
            for (int k = 0; k < 4; k++){
                float4 q = p[lane + k*32];
                v += (q.x + q.y) + (q.z + q.w);
            }
            v = warp_sum(v);
            if (lane == 0) s[r] = v;
        }
        __syncthreads();
        const float SCALE = 1.0f/11585.237502960395f;   // 1/512^1.5
        for (int r = w; r < D_; r += 8){
            float si = s[r];
            float z0 = si * s[lane     ] * SCALE;
            float z1 = si * s[lane + 32] * SCALE;
            float z2 = si * s[lane + 64] * SCALE;
            float m = warp_max(fmaxf(z0, fmaxf(z1, z2)));
            float e0 = expf(z0 - m), e1 = expf(z1 - m), e2 = expf(z2 - m);
            float inv = 1.f / warp_sum(e0 + e1 + e2);
            float* o = g_A + (b*D_ + r)*D_;
            o[lane]      = e0 * inv;
            o[lane + 32] = e1 * inv;
            o[lane + 64] = e2 * inv;
        }
        return;
    }
    if (bid < 276){
        // ---- colsum of W1: 4 blocks x 256 cols ----
        int col = (bid - 272)*256 + threadIdx.x;
        float s = 0.f;
        for (int k = 0; k < T_; k++) s += W1[(size_t)k*H_ + col];
        g_colsum[col] = s;
        return;
    }
    // ---- zero bn stats ----
    if (threadIdx.x < 2*D_) g_bnstats[threadIdx.x] = 0.f;
}

// K2: x1 = (I+A) @ X via fp16 mma; writes x1 in fp16 AND accumulates BN stats.
// grid (8 t-tiles x 16 b) = 128, 256 thr.
#define AT_SB_BYTES (128*208)
#define AT_ST_OFF   (AT_SB_BYTES + 96*144)          // stats region offset (bytes)
#define ATTN_SMEM   (AT_ST_OFF + 2*96*4)            // + sS[96] + sQ[96]
__global__ void __launch_bounds__(256) k_attn(const float* __restrict__ res){
    __half* sA = (__half*)dyn_smem;
    __half* sB = (__half*)(dyn_smem + AT_SB_BYTES);
    float*  sS = (float*)(dyn_smem + AT_ST_OFF);
    float*  sQ = sS + 96;
    uint32_t sbase = smem_u32(dyn_smem);
    int b  = blockIdx.x >> 3;
    int t0 = (blockIdx.x & 7) * 64;
    int tid = threadIdx.x, lane = tid & 31, w = tid >> 5;

    if (tid < 96){ sS[tid] = 0.f; sQ[tid] = 0.f; }
    for (int i = tid; i < D_*D_/4; i += 256){
        int d = (i*4)/D_, e = (i*4)%D_;
        float4 v = *(const float4*)&g_A[(b*D_+d)*D_ + e];
        *(__half2*)&sA[d*104 + e]     = __floats2half2_rn(v.x, v.y);
        *(__half2*)&sA[d*104 + e + 2] = __floats2half2_rn(v.z, v.w);
    }
    for (int i = tid; i < D_*16; i += 256){
        int e = i >> 4, t4 = (i & 15)*4;
        float4 v = *(const float4*)&res[(b*D_+e)*T_ + t0 + t4];
        *(__half2*)&sB[e*72 + t4]     = __floats2half2_rn(v.x, v.y);
        *(__half2*)&sB[e*72 + t4 + 2] = __floats2half2_rn(v.z, v.w);
    }
    __syncthreads();

    int wm = (w & 3) * 32, wn = (w >> 2) * 32;
    uint32_t aF0, aF1, bF0, bF1;
    {
        int rlo = lane & 7, mid = (lane >> 3) & 1, hi = lane >> 4;
        aF0 = sbase + (uint32_t)((wm + rlo + 8*mid)*208 + 16*hi);
        aF1 = aF0 + 16*208;
        bF0 = sbase + (uint32_t)(AT_SB_BYTES + (mid*8 + rlo)*144 + (wn + hi*8)*2);
        bF1 = bF0 + 32;
    }
    float4 acc[2][4];
    #pragma unroll
    for (int i = 0; i < 2; i++)
        #pragma unroll
        for (int j = 0; j < 4; j++) acc[i][j] = make_float4(0.f,0.f,0.f,0.f);

    #pragma unroll
    for (int ks = 0; ks < 6; ks++){
        uint32_t a0[4], a1[4], b0[4], b1[4];
        ldsm_x4 (a0, aF0 + ks*32);
        ldsm_x4 (a1, aF1 + ks*32);
        ldsm_x4t(b0, bF0 + ks*2304);
        ldsm_x4t(b1, bF1 + ks*2304);
        mma_f16(acc[0][0], a0, b0[0], b0[1]);
        mma_f16(acc[0][1], a0, b0[2], b0[3]);
        mma_f16(acc[0][2], a0, b1[0], b1[1]);
        mma_f16(acc[0][3], a0, b1[2], b1[3]);
        mma_f16(acc[1][0], a1, b0[0], b0[1]);
        mma_f16(acc[1][1], a1, b0[2], b0[3]);
        mma_f16(acc[1][2], a1, b1[0], b1[1]);
        mma_f16(acc[1][3], a1, b1[2], b1[3]);
    }

    if (wm < 96){
        int tr = lane >> 2, tc = lane & 3;
        float st[2][2] = {{0.f,0.f},{0.f,0.f}};   // [i][r0/r1] sums
        float sq[2][2] = {{0.f,0.f},{0.f,0.f}};   // sumsq
        #pragma unroll
        for (int i = 0; i < 2; i++){
            int r0 = wm + i*16 + tr;
            int r1 = r0 + 8;
            #pragma unroll
            for (int j = 0; j < 4; j++){
                int cl = wn + j*8 + tc*2;
                float4 v = acc[i][j];
                v.x += __half2float(sB[r0*72 + cl]);   v.y += __half2float(sB[r0*72 + cl+1]);
                v.z += __half2float(sB[r1*72 + cl]);   v.w += __half2float(sB[r1*72 + cl+1]);
                st[i][0] += v.x + v.y;  sq[i][0] += v.x*v.x + v.y*v.y;
                st[i][1] += v.z + v.w;  sq[i][1] += v.z*v.z + v.w*v.w;
                *(__half2*)&g_x1h[(size_t)(b*D_+r0)*T_ + t0 + cl] = __floats2half2_rn(v.x, v.y);
                *(__half2*)&g_x1h[(size_t)(b*D_+r1)*T_ + t0 + cl] = __floats2half2_rn(v.z, v.w);
            }
        }
        // reduce over tc (lanes tr*4+tc: bits 0-1)
        #pragma unroll
        for (int i = 0; i < 2; i++)
            #pragma unroll
            for (int r = 0; r < 2; r++){
                st[i][r] += __shfl_xor_sync(0xffffffffu, st[i][r], 1);
                st[i][r] += __shfl_xor_sync(0xffffffffu, st[i][r], 2);
                sq[i][r] += __shfl_xor_sync(0xffffffffu, sq[i][r], 1);
                sq[i][r] += __shfl_xor_sync(0xffffffffu, sq[i][r], 2);
            }
        if (tc == 0){
            #pragma unroll
            for (int i = 0; i < 2; i++){
                int r0 = wm + i*16 + tr;
                atomicAdd(&sS[r0],     st[i][0]);
                atomicAdd(&sQ[r0],     sq[i][0]);
                atomicAdd(&sS[r0 + 8], st[i][1]);
                atomicAdd(&sQ[r0 + 8], sq[i][1]);
            }
        }
    }
    __syncthreads();
    if (tid < 96){
        atomicAdd(&g_bnstats[tid],      sS[tid]);
        atomicAdd(&g_bnstats[D_ + tid], sQ[tid]);
    }
}

// K3: finalize BN scale/offset. 1 block, 96 threads.
__global__ void k_bnfin(const float* __restrict__ gamma, const float* __restrict__ beta){
    int d = threadIdx.x;
    const float invN = 1.f/(float)(B_*T_);
    float mean = g_bnstats[d] * invN;
    float var  = g_bnstats[D_+d] * invN - mean*mean;
    float rs = rsqrtf(var + 1e-5f);
    float sc = rs * gamma[d];
    g_bnscale[d] = sc;
    g_bnoff[d]   = beta[d] - mean * sc;
}

// ======================= fp16 mma.sync GEMM, 64x64 tiles (R12 proven core) =======================
// MODE 1 (GEMM1): out = half( GELU( sc_r*acc + of_r*colsum[c] + bias[c] ) )
// MODE 2 (GEMM2): split-K fp32 partials; lead adds bias + sc_r*Res + of_r
#define ASTG 9216    // 64*144
#define BSTG 9216
#define STG  (ASTG + BSTG)
#define GEMM_SMEM (3*STG)   // 55296

template<int MODE>
__global__ void __launch_bounds__(128) k_mma(
    const __half* __restrict__ A, const __half* __restrict__ Bw,
    const float* __restrict__ bias, const __half* __restrict__ Res,
    void* __restrict__ Cv, int M, int N, int K)
{
    uint32_t sbase = smem_u32(dyn_smem);
    int tid = threadIdx.x, lane = tid & 31, w = tid >> 5;
    int wm = (w & 1) * 32, wn = (w >> 1) * 32;
    int bn = blockIdx.x * 64, bm = blockIdx.y * 64;
    const bool SPLITK = (MODE == 2);
    int kz = SPLITK ? blockIdx.z : 0;
    int koff = SPLITK ? kz * (K >> 1) : 0;
    const int KT = (SPLITK ? (K >> 1) : K) / 64;
    bool lead = (!SPLITK) || (kz == 0);

    uint32_t aSm[4]; const __half* aG[4];
    uint32_t bSm[4]; const __half* bG[4];
    #pragma unroll
    for (int r = 0; r < 4; r++){
        int idx = tid + r*128, row = idx >> 3, c = idx & 7;
        aSm[r] = (uint32_t)(row*144 + c*16);
        aG[r]  = A + (size_t)(bm + row)*K + koff + c*8;
        bSm[r] = (uint32_t)(ASTG + row*144 + c*16);
        bG[r]  = Bw + (size_t)(koff + row)*N + bn + c*8;
    }

    uint32_t aF[2], bF[2];
    {
        int rlo = lane & 7, mid = (lane >> 3) & 1, hi = lane >> 4;
        aF[0] = (uint32_t)((wm + rlo + 8*mid)*144 + 16*hi);
        aF[1] = aF[0] + 16*144;
        bF[0] = (uint32_t)(ASTG + (mid*8 + rlo)*144 + (wn + hi*8)*2);
        bF[1] = bF[0] + 32;
    }

    float4 acc[2][4];
    #pragma unroll
    for (int i = 0; i < 2; i++)
        #pragma unroll
        for (int j = 0; j < 4; j++) acc[i][j] = make_float4(0.f,0.f,0.f,0.f);

    #pragma unroll
    for (int s = 0; s < 2; s++){
        uint32_t st = sbase + s*STG;
        #pragma unroll
        for (int r = 0; r < 4; r++){
            cp16(st + aSm[r], aG[r] + (size_t)s*64);
            cp16(st + bSm[r], bG[r] + (size_t)s*64*N);
        }
        CP_COMMIT();
    }

    int cur = 0, nxtbuf = 2;
    for (int kt = 0; kt < KT; kt++){
        if (kt < KT-1) CP_WAIT1(); else CP_WAIT0();
        __syncthreads();
        if (kt + 2 < KT){
            uint32_t st = sbase + nxtbuf*STG;
            #pragma unroll
            for (int r = 0; r < 4; r++){
                cp16(st + aSm[r], aG[r] + (size_t)(kt+2)*64);
                cp16(st + bSm[r], bG[r] + (size_t)(kt+2)*64*N);
            }
            CP_COMMIT();
        }
        uint32_t st = sbase + cur*STG;
        #pragma unroll
        for (int ks = 0; ks < 4; ks++){
            uint32_t a0[4], a1[4], b0[4], b1[4];
            ldsm_x4 (a0, st + aF[0] + ks*32);
            ldsm_x4 (a1, st + aF[1] + ks*32);
            ldsm_x4t(b0, st + bF[0] + ks*2304);
            ldsm_x4t(b1, st + bF[1] + ks*2304);
            mma_f16(acc[0][0], a0, b0[0], b0[1]);
            mma_f16(acc[0][1], a0, b0[2], b0[3]);
            mma_f16(acc[0][2], a0, b1[0], b1[1]);
            mma_f16(acc[0][3], a0, b1[2], b1[3]);
            mma_f16(acc[1][0], a1, b0[0], b0[1]);
            mma_f16(acc[1][1], a1, b0[2], b0[3]);
            mma_f16(acc[1][2], a1, b1[0], b1[1]);
            mma_f16(acc[1][3], a1, b1[2], b1[3]);
        }
        cur = (cur + 1 == 3) ? 0 : cur + 1;
        nxtbuf = (nxtbuf + 1 == 3) ? 0 : nxtbuf + 1;
    }

    int tr = lane >> 2, tc = lane & 3;
    #pragma unroll
    for (int i = 0; i < 2; i++){
        int r0 = bm + wm + i*16 + tr;
        int r1 = r0 + 8;
        float sc0 = 0.f, of0 = 0.f, sc1 = 0.f, of1 = 0.f;
        if (MODE == 1 || lead){
            int d0 = r0 % D_, d1 = r1 % D_;
            sc0 = g_bnscale[d0]; of0 = g_bnoff[d0];
            sc1 = g_bnscale[d1]; of1 = g_bnoff[d1];
        }
        #pragma unroll
        for (int j = 0; j < 4; j++){
            int col = bn + wn + j*8 + tc*2;
            float4 v = acc[i][j];
            if (MODE == 1){
                float2 bb = *(const float2*)&bias[col];
                float2 cs = *(const float2*)&g_colsum[col];
                v.x = fmaf(v.x, sc0, fmaf(of0, cs.x, bb.x));
                v.y = fmaf(v.y, sc0, fmaf(of0, cs.y, bb.y));
                v.z = fmaf(v.z, sc1, fmaf(of1, cs.x, bb.x));
                v.w = fmaf(v.w, sc1, fmaf(of1, cs.y, bb.y));
                v.x = 0.5f*v.x*(1.0f + erff(v.x*0.7071067811865476f));
                v.y = 0.5f*v.y*(1.0f + erff(v.y*0.7071067811865476f));
                v.z = 0.5f*v.z*(1.0f + erff(v.z*0.7071067811865476f));
                v.w = 0.5f*v.w*(1.0f + erff(v.w*0.7071067811865476f));
                __half* Ch = (__half*)Cv;
                *(__half2*)&Ch[(size_t)r0*N + col] = __floats2half2_rn(v.x, v.y);
                *(__half2*)&Ch[(size_t)r1*N + col] = __floats2half2_rn(v.z, v.w);
            } else {
                if (lead){
                    float2 bb = *(const float2*)&bias[col];
                    float2 f0 = __half22float2(*(const __half2*)&Res[(size_t)r0*N + col]);
                    float2 f1 = __half22float2(*(const __half2*)&Res[(size_t)r1*N + col]);
                    v.x += bb.x + fmaf(f0.x, sc0, of0);
                    v.y += bb.y + fmaf(f0.y, sc0, of0);
                    v.z += bb.x + fmaf(f1.x, sc1, of1);
                    v.w += bb.y + fmaf(f1.y, sc1, of1);
                }
                float* Cf = (float*)Cv + (size_t)kz * M * N;
                *(float2*)&Cf[(size_t)r0*N + col] = make_float2(v.x, v.y);
                *(float2*)&Cf[(size_t)r1*N + col] = make_float2(v.z, v.w);
            }
        }
    }
}

// K6: LayerNorm over T (sums the 2 split-K partials), write final output
__global__ void k_ln(const float* __restrict__ lng, const float* __restrict__ lnb,
                     float* __restrict__ out){
    int row = blockIdx.x;
    const float* y0 = g_y + (size_t)row*T_;
    const float* y1 = g_y + (size_t)(B_*D_)*T_ + (size_t)row*T_;
    int tid = threadIdx.x;
    float a = y0[tid]       + y1[tid];
    float b = y0[tid + 256] + y1[tid + 256];
    __shared__ float red[8];
    int w = tid >> 5;
    float s = warp_sum(a + b);
    if ((tid & 31) == 0) red[w] = s;
    __syncthreads();
    float S = 0.f;
    #pragma unroll
    for (int k = 0; k < 8; k++) S += red[k];
    float mean = S * (1.f/512.f);
    float d0 = a - mean, d1 = b - mean;
    __syncthreads();
    float ss = warp_sum(d0*d0 + d1*d1);
    if ((tid & 31) == 0) red[w] = ss;
    __syncthreads();
    float SS = 0.f;
    #pragma unroll
    for (int k = 0; k < 8; k++) SS += red[k];
    float rs = rsqrtf(SS * (1.f/512.f) + 1e-5f);
    out[row*T_ + tid]       = d0*rs*lng[tid]       + lnb[tid];
    out[row*T_ + tid + 256] = d1*rs*lng[tid + 256] + lnb[tid + 256];
}

extern "C" void kernel_launch(void* const* d_in, const int* in_sizes, int n_in,
                              void* d_out, int out_size){
    const float* residual = (const float*)d_in[0];
    const float* bn_g = (const float*)d_in[1];
    const float* bn_b = (const float*)d_in[2];
    const float* ln_g = (const float*)d_in[3];
    const float* ln_b = (const float*)d_in[4];
    const float* W1   = (const float*)d_in[5];
    const float* b1   = (const float*)d_in[6];
    const float* W2   = (const float*)d_in[7];
    const float* b2   = (const float*)d_in[8];
    float* out = (float*)d_out;

    cudaFuncSetAttribute(k_attn, cudaFuncAttributeMaxDynamicSharedMemorySize, ATTN_SMEM);
    cudaFuncSetAttribute(k_mma<1>, cudaFuncAttributeMaxDynamicSharedMemorySize, GEMM_SMEM);
    cudaFuncSetAttribute(k_mma<2>, cudaFuncAttributeMaxDynamicSharedMemorySize, GEMM_SMEM);

    __half *px1h, *ph, *pw1h, *pw2h;
    float *py;
    cudaGetSymbolAddress((void**)&px1h, g_x1h);
    cudaGetSymbolAddress((void**)&ph,   g_h);
    cudaGetSymbolAddress((void**)&py,   g_y);
    cudaGetSymbolAddress((void**)&pw1h, g_w1h);
    cudaGetSymbolAddress((void**)&pw2h, g_w2h);

    // conversion (256) + corr (16) + colsum (4) + zero stats (1)
    k_pre<<<277, 256>>>(W1, pw1h, W2, pw2h, residual);

    k_attn<<<128, 256, ATTN_SMEM>>>(residual);

    k_bnfin<<<1, 96>>>(bn_g, bn_b);

    // GEMM1: h = half( GELU( sc*(x1h @ W1) + of*colsum + b1 ) )  [1536 x 1024 x 512]
    dim3 g1(H_/64, (B_*D_)/64);
    k_mma<1><<<g1, 128, GEMM_SMEM>>>(px1h, pw1h, b1, nullptr, ph, B_*D_, H_, T_);
    // GEMM2: y = h @ W2 + b2 + BN(x1h), split-K x2  [1536 x 512 x 1024]
    dim3 g2(T_/64, (B_*D_)/64, 2);
    k_mma<2><<<g2, 128, GEMM_SMEM>>>(ph, pw2h, b2, px1h, py, B_*D_, T_, H_);

    k_ln<<<B_*D_, 256>>>(ln_g, ln_b, out);
}

// round 17
// speedup vs baseline: 1.0449x; 1.0449x over previous
#include <cuda_runtime.h>
#include <cuda_fp16.h>
#include <math.h>
#include <stdint.h>

#define B_  16
#define D_  96
#define T_  512
#define H_  1024
#define BD_ (B_*D_)

// ---- scratch ----
__device__ float  g_A[B_*D_*D_];    // softmax corr (fp32)
__device__ float  g_x1[BD_*T_];     // attn+res (fp32, for BN stats)
__device__ __half g_x2r[BD_*T_];    // BN(x1) fp16 (GEMM1 A + GEMM2 residual)
__device__ __half g_h[BD_*H_];      // GELU output fp16
__device__ float  g_y[2*BD_*T_];    // GEMM2 split-K partials (fp32)
__device__ __half g_w1h[T_*H_];     // W1 [T][H] fp16 (natural layout)
__device__ __half g_w2h[H_*T_];     // W2 [H][T] fp16 (natural layout)

extern __shared__ char dyn_smem[];

__device__ __forceinline__ float warp_sum(float v){
    #pragma unroll
    for(int o=16;o>0;o>>=1) v += __shfl_xor_sync(0xffffffffu, v, o);
    return v;
}
__device__ __forceinline__ float warp_max(float v){
    #pragma unroll
    for(int o=16;o>0;o>>=1) v = fmaxf(v, __shfl_xor_sync(0xffffffffu, v, o));
    return v;
}
__device__ __forceinline__ uint32_t smem_u32(const void* p){
    uint32_t a;
    asm("{ .reg .u64 t; cvta.to.shared.u64 t, %1; cvt.u32.u64 %0, t; }" : "=r"(a) : "l"(p));
    return a;
}
__device__ __forceinline__ void mma_f16(float4& d, const uint32_t a[4], uint32_t b0, uint32_t b1){
    asm volatile("mma.sync.aligned.m16n8k16.row.col.f32.f16.f16.f32 "
        "{%0,%1,%2,%3}, {%4,%5,%6,%7}, {%8,%9}, {%0,%1,%2,%3};"
        : "+f"(d.x), "+f"(d.y), "+f"(d.z), "+f"(d.w)
        : "r"(a[0]), "r"(a[1]), "r"(a[2]), "r"(a[3]), "r"(b0), "r"(b1));
}
__device__ __forceinline__ void ldsm_x4(uint32_t* r, uint32_t addr){
    asm volatile("ldmatrix.sync.aligned.m8n8.x4.shared.b16 {%0,%1,%2,%3}, [%4];"
        : "=r"(r[0]), "=r"(r[1]), "=r"(r[2]), "=r"(r[3]) : "r"(addr));
}
__device__ __forceinline__ void ldsm_x4t(uint32_t* r, uint32_t addr){
    asm volatile("ldmatrix.sync.aligned.m8n8.x4.trans.shared.b16 {%0,%1,%2,%3}, [%4];"
        : "=r"(r[0]), "=r"(r[1]), "=r"(r[2]), "=r"(r[3]) : "r"(addr));
}
__device__ __forceinline__ void cp16(uint32_t dst, const void* src){
    asm volatile("cp.async.ca.shared.global [%0], [%1], 16;" :: "r"(dst), "l"(src));
}
#define CP_COMMIT() asm volatile("cp.async.commit_group;" ::: "memory")
#define CP_WAIT1()  asm volatile("cp.async.wait_group 1;" ::: "memory")
#define CP_WAIT0()  asm volatile("cp.async.wait_group 0;" ::: "memory")

// K0: fp32->fp16 weight convert + corr softmax. grid 272 x 256. (R12 proven)
__global__ void k_pre(const float* __restrict__ W1, __half* __restrict__ W1h,
                      const float* __restrict__ W2, __half* __restrict__ W2h,
                      const float* __restrict__ res){
    int bid = blockIdx.x;
    if (bid < 256){
        const float* W = (bid < 128) ? W1 : W2;
        __half* Wh = (bid < 128) ? W1h : W2h;
        int base = (bid & 127) * 4096;
        #pragma unroll
        for (int i = 0; i < 4; i++){
            int idx = base + (threadIdx.x + i*256)*4;
            float4 v = *(const float4*)&W[idx];
            *(__half2*)&Wh[idx]     = __floats2half2_rn(v.x, v.y);
            *(__half2*)&Wh[idx + 2] = __floats2half2_rn(v.z, v.w);
        }
        return;
    }
    __shared__ float s[D_];
    int b = bid - 256;
    int w = threadIdx.x >> 5, lane = threadIdx.x & 31;
    for (int r = w; r < D_; r += 8){
        const float4* p = (const float4*)(res + (b*D_ + r)*T_);
        float v = 0.f;
        #pragma unroll
        for (int k = 0; k < 4; k++){
            float4 q = p[lane + k*32];
            v += (q.x + q.y) + (q.z + q.w);
        }
        v = warp_sum(v);
        if (lane == 0) s[r] = v;
    }
    __syncthreads();
    const float SCALE = 1.0f/11585.237502960395f;   // 1/512^1.5
    for (int r = w; r < D_; r += 8){
        float si = s[r];
        float z0 = si * s[lane     ] * SCALE;
        float z1 = si * s[lane + 32] * SCALE;
        float z2 = si * s[lane + 64] * SCALE;
        float m = warp_max(fmaxf(z0, fmaxf(z1, z2)));
        float e0 = expf(z0 - m), e1 = expf(z1 - m), e2 = expf(z2 - m);
        float inv = 1.f / warp_sum(e0 + e1 + e2);
        float* o = g_A + (b*D_ + r)*D_;
        o[lane]      = e0 * inv;
        o[lane + 32] = e1 * inv;
        o[lane + 64] = e2 * inv;
    }
}

// K2: x1 = (I+A) @ X via fp16 mma. grid (T/64, B), 256 thr. (R12 proven)
#define AT_SB_BYTES (128*208)
#define ATTN_SMEM   (AT_SB_BYTES + 96*144)   // 40448 B
__global__ void __launch_bounds__(256) k_attn(const float* __restrict__ res){
    __half* sA = (__half*)dyn_smem;
    __half* sB = (__half*)(dyn_smem + AT_SB_BYTES);
    uint32_t sbase = smem_u32(dyn_smem);
    int b  = blockIdx.y;
    int t0 = blockIdx.x * 64;
    int tid = threadIdx.x, lane = tid & 31, w = tid >> 5;

    for (int i = tid; i < D_*D_/4; i += 256){
        int d = (i*4)/D_, e = (i*4)%D_;
        float4 v = *(const float4*)&g_A[(b*D_+d)*D_ + e];
        *(__half2*)&sA[d*104 + e]     = __floats2half2_rn(v.x, v.y);
        *(__half2*)&sA[d*104 + e + 2] = __floats2half2_rn(v.z, v.w);
    }
    for (int i = tid; i < D_*16; i += 256){
        int e = i >> 4, t4 = (i & 15)*4;
        float4 v = *(const float4*)&res[(b*D_+e)*T_ + t0 + t4];
        *(__half2*)&sB[e*72 + t4]     = __floats2half2_rn(v.x, v.y);
        *(__half2*)&sB[e*72 + t4 + 2] = __floats2half2_rn(v.z, v.w);
    }
    __syncthreads();

    int wm = (w & 3) * 32, wn = (w >> 2) * 32;
    uint32_t aF0, aF1, bF0, bF1;
    {
        int rlo = lane & 7, mid = (lane >> 3) & 1, hi = lane >> 4;
        aF0 = sbase + (uint32_t)((wm + rlo + 8*mid)*208 + 16*hi);
        aF1 = aF0 + 16*208;
        bF0 = sbase + (uint32_t)(AT_SB_BYTES + (mid*8 + rlo)*144 + (wn + hi*8)*2);
        bF1 = bF0 + 32;
    }
    float4 acc[2][4];
    #pragma unroll
    for (int i = 0; i < 2; i++)
        #pragma unroll
        for (int j = 0; j < 4; j++) acc[i][j] = make_float4(0.f,0.f,0.f,0.f);

    #pragma unroll
    for (int ks = 0; ks < 6; ks++){
        uint32_t a0[4], a1[4], b0[4], b1[4];
        ldsm_x4 (a0, aF0 + ks*32);
        ldsm_x4 (a1, aF1 + ks*32);
        ldsm_x4t(b0, bF0 + ks*2304);
        ldsm_x4t(b1, bF1 + ks*2304);
        mma_f16(acc[0][0], a0, b0[0], b0[1]);
        mma_f16(acc[0][1], a0, b0[2], b0[3]);
        mma_f16(acc[0][2], a0, b1[0], b1[1]);
        mma_f16(acc[0][3], a0, b1[2], b1[3]);
        mma_f16(acc[1][0], a1, b0[0], b0[1]);
        mma_f16(acc[1][1], a1, b0[2], b0[3]);
        mma_f16(acc[1][2], a1, b1[0], b1[1]);
        mma_f16(acc[1][3], a1, b1[2], b1[3]);
    }

    if (wm < 96){
        int tr = lane >> 2, tc = lane & 3;
        #pragma unroll
        for (int i = 0; i < 2; i++){
            int r0 = wm + i*16 + tr;
            int r1 = r0 + 8;
            #pragma unroll
            for (int j = 0; j < 4; j++){
                int cl = wn + j*8 + tc*2;
                float4 v = acc[i][j];
                v.x += __half2float(sB[r0*72 + cl]);   v.y += __half2float(sB[r0*72 + cl+1]);
                v.z += __half2float(sB[r1*72 + cl]);   v.w += __half2float(sB[r1*72 + cl+1]);
                *(float2*)&g_x1[(b*D_+r0)*T_ + t0 + cl] = make_float2(v.x, v.y);
                *(float2*)&g_x1[(b*D_+r1)*T_ + t0 + cl] = make_float2(v.z, v.w);
            }
        }
    }
}

// K3: fused BN stats + apply (single read), write half. grid=D_, 512 thr. (R12 proven)
__global__ void k_bn(const float* __restrict__ gamma, const float* __restrict__ beta){
    int d = blockIdx.x;
    int tid = threadIdx.x;
    float4 v[4];
    float s = 0.f, ss = 0.f;
    #pragma unroll
    for (int r = 0; r < 4; r++){
        int i = tid + r*512;
        int b = i >> 7, t4 = i & 127;
        v[r] = *(const float4*)&g_x1[(b*D_+d)*T_ + t4*4];
        s  += (v[r].x + v[r].y) + (v[r].z + v[r].w);
        ss += (v[r].x*v[r].x + v[r].y*v[r].y) + (v[r].z*v[r].z + v[r].w*v[r].w);
    }
    s = warp_sum(s); ss = warp_sum(ss);
    __shared__ float r1[16], r2[16];
    __shared__ float bsc, bof;
    int w = tid >> 5;
    if ((tid & 31) == 0){ r1[w] = s; r2[w] = ss; }
    __syncthreads();
    if (tid == 0){
        float S = 0.f, SS = 0.f;
        #pragma unroll
        for (int k = 0; k < 16; k++){ S += r1[k]; SS += r2[k]; }
        const float invN = 1.f/(float)(B_*T_);
        float mean = S * invN;
        float var  = SS * invN - mean*mean;
        float rs = rsqrtf(var + 1e-5f);
        float sc = rs * gamma[d];
        bsc = sc; bof = beta[d] - mean * sc;
    }
    __syncthreads();
    float sc = bsc, of = bof;
    #pragma unroll
    for (int r = 0; r < 4; r++){
        int i = tid + r*512;
        int b = i >> 7, t4 = i & 127;
        float4 q = v[r];
        __half* dst = g_x2r + (b*D_+d)*T_ + t4*4;
        *(__half2*)dst       = __floats2half2_rn(fmaf(q.x, sc, of), fmaf(q.y, sc, of));
        *(__half2*)(dst + 2) = __floats2half2_rn(fmaf(q.z, sc, of), fmaf(q.w, sc, of));
    }
}

// ======================= fp16 mma.sync GEMM, 64 x BN tiles, 128 thr =======================
// C = epi( A[M,K] @ W[K,N] + bias [+ Res] ); W natural [K][N]; B frags via ldsm.trans.
// 4 warps (2m x 2n): warp tile 32 x (BN/2). 3-stage cp.async. BN=128 (GEMM1) or 64 (GEMM2).
#define ASTG 9216    // 64*144

template<int BN, bool GELU, bool HALF_OUT, bool RESID, bool SPLITK>
__global__ void __launch_bounds__(128) k_mma(
    const __half* __restrict__ A, const __half* __restrict__ Bw,
    const float* __restrict__ bias, const __half* __restrict__ Res,
    void* __restrict__ Cv, int M, int N, int K)
{
    constexpr int BROW = BN*2 + 16;       // B row stride bytes (144 or 272)
    constexpr int BSTG = 64*BROW;
    constexpr int STG  = ASTG + BSTG;
    constexpr int NBC  = BN/16;           // B 16B-chunks per thread (4 or 8)
    constexpr int NBL  = BN/32;           // trans-LDSM per warp per ks (2 or 4)

    uint32_t sbase = smem_u32(dyn_smem);
    int tid = threadIdx.x, lane = tid & 31, w = tid >> 5;
    int wm = (w & 1) * 32, wn = (w >> 1) * (BN/2);
    int bn = blockIdx.x * BN, bm = blockIdx.y * 64;
    int kz = SPLITK ? blockIdx.z : 0;
    int koff = SPLITK ? kz * (K >> 1) : 0;
    const int KT = (SPLITK ? (K >> 1) : K) / 64;
    bool lead = (!SPLITK) || (kz == 0);

    uint32_t aSm[4]; const __half* aG[4];
    #pragma unroll
    for (int r = 0; r < 4; r++){
        int idx = tid + r*128, row = idx >> 3, c = idx & 7;
        aSm[r] = (uint32_t)(row*144 + c*16);
        aG[r]  = A + (size_t)(bm + row)*K + koff + c*8;
    }
    uint32_t bSm[NBC]; const __half* bG[NBC];
    #pragma unroll
    for (int r = 0; r < NBC; r++){
        int idx = tid + r*128, row = idx / (BN/8), c = idx % (BN/8);
        bSm[r] = (uint32_t)(ASTG + row*BROW + c*16);
        bG[r]  = Bw + (size_t)(koff + row)*N + bn + c*8;
    }

    uint32_t aF[2], bF[NBL];
    {
        int rlo = lane & 7, mid = (lane >> 3) & 1, hi = lane >> 4;
        aF[0] = (uint32_t)((wm + rlo + 8*mid)*144 + 16*hi);
        aF[1] = aF[0] + 16*144;
        #pragma unroll
        for (int l = 0; l < NBL; l++)
            bF[l] = (uint32_t)(ASTG + (mid*8 + rlo)*BROW + (wn + l*16 + hi*8)*2);
    }

    float4 acc[2][2*NBL];
    #pragma unroll
    for (int i = 0; i < 2; i++)
        #pragma unroll
        for (int j = 0; j < 2*NBL; j++) acc[i][j] = make_float4(0.f,0.f,0.f,0.f);

    #pragma unroll
    for (int s = 0; s < 2; s++){
        uint32_t st = sbase + s*STG;
        #pragma unroll
        for (int r = 0; r < 4; r++)   cp16(st + aSm[r], aG[r] + (size_t)s*64);
        #pragma unroll
        for (int r = 0; r < NBC; r++) cp16(st + bSm[r], bG[r] + (size_t)s*64*N);
        CP_COMMIT();
    }

    int cur = 0, nxtbuf = 2;
    for (int kt = 0; kt < KT; kt++){
        if (kt < KT-1) CP_WAIT1(); else CP_WAIT0();
        __syncthreads();
        if (kt + 2 < KT){
            uint32_t st = sbase + nxtbuf*STG;
            #pragma unroll
            for (int r = 0; r < 4; r++)   cp16(st + aSm[r], aG[r] + (size_t)(kt+2)*64);
            #pragma unroll
            for (int r = 0; r < NBC; r++) cp16(st + bSm[r], bG[r] + (size_t)(kt+2)*64*N);
            CP_COMMIT();
        }
        uint32_t st = sbase + cur*STG;
        #pragma unroll
        for (int ks = 0; ks < 4; ks++){        // 4 x k16 = 64
            uint32_t a0[4], a1[4], bfr[NBL][4];
            ldsm_x4 (a0, st + aF[0] + ks*32);
            ldsm_x4 (a1, st + aF[1] + ks*32);
            #pragma unroll
            for (int l = 0; l < NBL; l++)
                ldsm_x4t(bfr[l], st + bF[l] + ks*16*BROW);
            #pragma unroll
            for (int l = 0; l < NBL; l++){
                mma_f16(acc[0][2*l  ], a0, bfr[l][0], bfr[l][1]);
                mma_f16(acc[0][2*l+1], a0, bfr[l][2], bfr[l][3]);
                mma_f16(acc[1][2*l  ], a1, bfr[l][0], bfr[l][1]);
                mma_f16(acc[1][2*l+1], a1, bfr[l][2], bfr[l][3]);
            }
        }
        cur = (cur + 1 == 3) ? 0 : cur + 1;
        nxtbuf = (nxtbuf + 1 == 3) ? 0 : nxtbuf + 1;
    }

    int tr = lane >> 2, tc = lane & 3;
    #pragma unroll
    for (int i = 0; i < 2; i++){
        int r0 = bm + wm + i*16 + tr;
        int r1 = r0 + 8;
        #pragma unroll
        for (int j = 0; j < 2*NBL; j++){
            int col = bn + wn + j*8 + tc*2;
            float4 v = acc[i][j];
            if (lead){
                float2 bb = *(const float2*)&bias[col];
                v.x += bb.x; v.y += bb.y; v.z += bb.x; v.w += bb.y;
            }
            if (GELU){
                v.x = 0.5f*v.x*(1.0f + erff(v.x*0.7071067811865476f));
                v.y = 0.5f*v.y*(1.0f + erff(v.y*0.7071067811865476f));
                v.z = 0.5f*v.z*(1.0f + erff(v.z*0.7071067811865476f));
                v.w = 0.5f*v.w*(1.0f + erff(v.w*0.7071067811865476f));
            }
            if (RESID && lead){
                float2 f0 = __half22float2(*(const __half2*)&Res[(size_t)r0*N + col]);
                float2 f1 = __half22float2(*(const __half2*)&Res[(size_t)r1*N + col]);
                v.x += f0.x; v.y += f0.y; v.z += f1.x; v.w += f1.y;
            }
            if (HALF_OUT){
                __half* Ch = (__half*)Cv;
                *(__half2*)&Ch[(size_t)r0*N + col] = __floats2half2_rn(v.x, v.y);
                *(__half2*)&Ch[(size_t)r1*N + col] = __floats2half2_rn(v.z, v.w);
            } else {
                float* Cf = (float*)Cv + (SPLITK ? (size_t)kz * M * N : 0);
                *(float2*)&Cf[(size_t)r0*N + col] = make_float2(v.x, v.y);
                *(float2*)&Cf[(size_t)r1*N + col] = make_float2(v.z, v.w);
            }
        }
    }
}

// K6: LayerNorm over T (sums the 2 split-K partials), write final output
__global__ void k_ln(const float* __restrict__ lng, const float* __restrict__ lnb,
                     float* __restrict__ out){
    int row = blockIdx.x;
    const float* y0 = g_y + (size_t)row*T_;
    const float* y1 = g_y + (size_t)BD_*T_ + (size_t)row*T_;
    int tid = threadIdx.x;
    float a = y0[tid]       + y1[tid];
    float b = y0[tid + 256] + y1[tid + 256];
    __shared__ float red[8];
    int w = tid >> 5;
    float s = warp_sum(a + b);
    if ((tid & 31) == 0) red[w] = s;
    __syncthreads();
    float S = 0.f;
    #pragma unroll
    for (int k = 0; k < 8; k++) S += red[k];
    float mean = S * (1.f/512.f);
    float d0 = a - mean, d1 = b - mean;
    __syncthreads();
    float ss = warp_sum(d0*d0 + d1*d1);
    if ((tid & 31) == 0) red[w] = ss;
    __syncthreads();
    float SS = 0.f;
    #pragma unroll
    for (int k = 0; k < 8; k++) SS += red[k];
    float rs = rsqrtf(SS * (1.f/512.f) + 1e-5f);
    out[row*T_ + tid]       = d0*rs*lng[tid]       + lnb[tid];
    out[row*T_ + tid + 256] = d1*rs*lng[tid + 256] + lnb[tid + 256];
}

extern "C" void kernel_launch(void* const* d_in, const int* in_sizes, int n_in,
                              void* d_out, int out_size){
    const float* residual = (const float*)d_in[0];
    const float* bn_g = (const float*)d_in[1];
    const float* bn_b = (const float*)d_in[2];
    const float* ln_g = (const float*)d_in[3];
    const float* ln_b = (const float*)d_in[4];
    const float* W1   = (const float*)d_in[5];
    const float* b1   = (const float*)d_in[6];
    const float* W2   = (const float*)d_in[7];
    const float* b2   = (const float*)d_in[8];
    float* out = (float*)d_out;

    const int g1_smem = 3*(ASTG + 64*(128*2+16));   // 3*(9216+17408) = 79872
    const int g2_smem = 3*(ASTG + 64*(64*2+16));    // 3*(9216+9216)  = 55296
    cudaFuncSetAttribute(k_attn, cudaFuncAttributeMaxDynamicSharedMemorySize, ATTN_SMEM);
    cudaFuncSetAttribute(k_mma<128, true,  true,  false, false>, cudaFuncAttributeMaxDynamicSharedMemorySize, g1_smem);
    cudaFuncSetAttribute(k_mma<64,  false, false, true,  true >, cudaFuncAttributeMaxDynamicSharedMemorySize, g2_smem);

    __half *px2r, *ph, *pw1h, *pw2h;
    float *py;
    cudaGetSymbolAddress((void**)&px2r, g_x2r);
    cudaGetSymbolAddress((void**)&ph,   g_h);
    cudaGetSymbolAddress((void**)&py,   g_y);
    cudaGetSymbolAddress((void**)&pw1h, g_w1h);
    cudaGetSymbolAddress((void**)&pw2h, g_w2h);

    k_pre<<<256 + B_, 256>>>(W1, pw1h, W2, pw2h, residual);

    dim3 ga(T_/64, B_);
    k_attn<<<ga, 256, ATTN_SMEM>>>(residual);
    k_bn<<<D_, 512>>>(bn_g, bn_b);

    // GEMM1: h = half( GELU(x2r @ W1 + b1) )   [1536 x 1024 x 512], 64x128 tiles, 192 CTAs
    dim3 g1(H_/128, BD_/64);
    k_mma<128, true,  true,  false, false><<<g1, 128, g1_smem>>>(px2r, pw1h, b1, nullptr, ph, BD_, H_, T_);
    // GEMM2: y = h @ W2 + b2 + x2r, split-K x2  [1536 x 512 x 1024], 64x64 tiles, 384 CTAs
    dim3 g2(T_/64, BD_/64, 2);
    k_mma<64,  false, false, true,  true ><<<g2, 128, g2_smem>>>(ph, pw2h, b2, px2r, py, BD_, T_, H_);

    k_ln<<<BD_, 256>>>(ln_g, ln_b, out);
}